// round 1
// baseline (speedup 1.0000x reference)
#include <cuda_runtime.h>
#include <cstddef>

// Problem constants
#define BB   32
#define HH   32
#define WW   32
#define CC   256
#define SS   (HH * WW)        // 1024 spatial positions
#define GG   32               // groups
#define CPG  (CC / GG)        // 8 channels per group
#define MS   (BB * SS)        // 32768 rows for the big projections
#define EPS  1e-5f

// ---------------------------------------------------------------------------
// Scratch (static device globals — no runtime allocation allowed)
// ---------------------------------------------------------------------------
__device__ float g_ft[(size_t)BB * SS * CC];      // groupnorm output
__device__ float g_q [(size_t)BB * SS * CC];
__device__ float g_k [(size_t)BB * SS * CC];
__device__ float g_v [(size_t)BB * SS * CC];
__device__ float g_lg[(size_t)BB * SS * SS];      // logits / softmax weights
__device__ float g_at[(size_t)BB * SS * CC];      // attention output (pre-Wo)

// ---------------------------------------------------------------------------
// GroupNorm: one block per (batch, group). 256 threads, 8192 elems per group.
// ---------------------------------------------------------------------------
__global__ void gn_kernel(const float* __restrict__ x,
                          const float* __restrict__ scale,
                          const float* __restrict__ bias,
                          float* __restrict__ ft)
{
    const int b   = blockIdx.x / GG;
    const int g   = blockIdx.x % GG;
    const int tid = threadIdx.x;            // 0..255

    const float* xb = x + (size_t)b * SS * CC + g * CPG;

    float sum = 0.f, ssq = 0.f;
#pragma unroll
    for (int kk = 0; kk < 4; kk++) {
        const int s = tid + kk * 256;
        const float4* p = (const float4*)(xb + (size_t)s * CC);
        float4 a = p[0];
        float4 c = p[1];
        sum += a.x + a.y + a.z + a.w + c.x + c.y + c.z + c.w;
        ssq += a.x*a.x + a.y*a.y + a.z*a.z + a.w*a.w
             + c.x*c.x + c.y*c.y + c.z*c.z + c.w*c.w;
    }

    __shared__ float r0[256];
    __shared__ float r1[256];
    r0[tid] = sum; r1[tid] = ssq;
    __syncthreads();
    for (int off = 128; off > 0; off >>= 1) {
        if (tid < off) { r0[tid] += r0[tid + off]; r1[tid] += r1[tid + off]; }
        __syncthreads();
    }
    const float mean = r0[0] * (1.f / 8192.f);
    const float var  = r1[0] * (1.f / 8192.f) - mean * mean;
    const float inv  = rsqrtf(var + EPS);

    float sc[CPG], bi[CPG];
#pragma unroll
    for (int c = 0; c < CPG; c++) {
        sc[c] = scale[g * CPG + c] * inv;
        bi[c] = bias [g * CPG + c];
    }

    float* fb = ft + (size_t)b * SS * CC + g * CPG;
#pragma unroll
    for (int kk = 0; kk < 4; kk++) {
        const int s = tid + kk * 256;
        const float* xi = xb + (size_t)s * CC;
        float*       fo = fb + (size_t)s * CC;
#pragma unroll
        for (int c = 0; c < CPG; c++)
            fo[c] = (xi[c] - mean) * sc[c] + bi[c];
    }
}

// ---------------------------------------------------------------------------
// Tiled SGEMM: C[m,n] = alpha * sum_k A[m,k] * B'[k,n]  (+bias[n]) (+resid[m,n])
//   TRANSB=0: B stored [K,N] (ldb=N).  TRANSB=1: B stored [N,K] (ldb=K).
// Tile 64x64, BK=16, 256 threads, 4x4 per thread. Batched via blockIdx.z.
// Requires M%64==0, N%64==0, K%16==0 (all shapes here satisfy this).
// ---------------------------------------------------------------------------
template <int TRANSB>
__global__ void sgemm64(const float* __restrict__ A,
                        const float* __restrict__ B,
                        const float* __restrict__ bias,
                        const float* __restrict__ resid,
                        float* __restrict__ Cout,
                        int M, int N, int K, float alpha,
                        long long sA, long long sB, long long sC)
{
    const int batch = blockIdx.z;
    A    += (size_t)batch * sA;
    B    += (size_t)batch * sB;
    Cout += (size_t)batch * sC;

    __shared__ float As[16][64];
    __shared__ float Bs[16][64];

    const int tid  = threadIdx.x;
    const int tx   = tid & 15;
    const int ty   = tid >> 4;
    const int row0 = blockIdx.x * 64;
    const int col0 = blockIdx.y * 64;

    float acc[4][4] = {};

    for (int k0 = 0; k0 < K; k0 += 16) {
        // Load A tile (64 rows x 16 k), store transposed into As[k][m]
        {
            const int r  = tid >> 2;
            const int kc = (tid & 3) * 4;
            float4 a = *(const float4*)&A[(size_t)(row0 + r) * K + k0 + kc];
            As[kc + 0][r] = a.x; As[kc + 1][r] = a.y;
            As[kc + 2][r] = a.z; As[kc + 3][r] = a.w;
        }
        // Load B tile (16 k x 64 n)
        if (TRANSB) {
            const int nr = tid >> 2;
            const int kc = (tid & 3) * 4;
            float4 bv = *(const float4*)&B[(size_t)(col0 + nr) * K + k0 + kc];
            Bs[kc + 0][nr] = bv.x; Bs[kc + 1][nr] = bv.y;
            Bs[kc + 2][nr] = bv.z; Bs[kc + 3][nr] = bv.w;
        } else {
            const int kr = tid >> 4;
            const int nc = (tid & 15) * 4;
            float4 bv = *(const float4*)&B[(size_t)(k0 + kr) * N + col0 + nc];
            *(float4*)&Bs[kr][nc] = bv;
        }
        __syncthreads();

#pragma unroll
        for (int kk = 0; kk < 16; kk++) {
            const float4 ra = *(const float4*)&As[kk][ty * 4];
            const float4 rb = *(const float4*)&Bs[kk][tx * 4];
            acc[0][0] += ra.x * rb.x; acc[0][1] += ra.x * rb.y;
            acc[0][2] += ra.x * rb.z; acc[0][3] += ra.x * rb.w;
            acc[1][0] += ra.y * rb.x; acc[1][1] += ra.y * rb.y;
            acc[1][2] += ra.y * rb.z; acc[1][3] += ra.y * rb.w;
            acc[2][0] += ra.z * rb.x; acc[2][1] += ra.z * rb.y;
            acc[2][2] += ra.z * rb.z; acc[2][3] += ra.z * rb.w;
            acc[3][0] += ra.w * rb.x; acc[3][1] += ra.w * rb.y;
            acc[3][2] += ra.w * rb.z; acc[3][3] += ra.w * rb.w;
        }
        __syncthreads();
    }

    // Epilogue: alpha, +bias, +residual, float4 stores
    float4 bb = make_float4(0.f, 0.f, 0.f, 0.f);
    if (bias) bb = *(const float4*)&bias[col0 + tx * 4];

#pragma unroll
    for (int i = 0; i < 4; i++) {
        const int r = row0 + ty * 4 + i;
        float4 o = make_float4(acc[i][0] * alpha + bb.x,
                               acc[i][1] * alpha + bb.y,
                               acc[i][2] * alpha + bb.z,
                               acc[i][3] * alpha + bb.w);
        if (resid) {
            float4 rr = *(const float4*)&resid[(size_t)r * N + col0 + tx * 4];
            o.x += rr.x; o.y += rr.y; o.z += rr.z; o.w += rr.w;
        }
        *(float4*)&Cout[(size_t)r * N + col0 + tx * 4] = o;
    }
}

// ---------------------------------------------------------------------------
// Row softmax over 1024 columns, one block (256 threads) per row, float4 I/O.
// ---------------------------------------------------------------------------
__global__ void softmax_kernel(float* __restrict__ lg)
{
    const size_t row = blockIdx.x;
    float4* p = (float4*)(lg + row * (size_t)SS);
    const int tid = threadIdx.x;

    float4 v = p[tid];
    float m = fmaxf(fmaxf(v.x, v.y), fmaxf(v.z, v.w));

    __shared__ float red[256];
    red[tid] = m;
    __syncthreads();
    for (int off = 128; off > 0; off >>= 1) {
        if (tid < off) red[tid] = fmaxf(red[tid], red[tid + off]);
        __syncthreads();
    }
    m = red[0];
    __syncthreads();

    v.x = expf(v.x - m); v.y = expf(v.y - m);
    v.z = expf(v.z - m); v.w = expf(v.w - m);
    float s = v.x + v.y + v.z + v.w;

    red[tid] = s;
    __syncthreads();
    for (int off = 128; off > 0; off >>= 1) {
        if (tid < off) red[tid] += red[tid + off];
        __syncthreads();
    }
    const float inv = 1.f / red[0];

    v.x *= inv; v.y *= inv; v.z *= inv; v.w *= inv;
    p[tid] = v;
}

// ---------------------------------------------------------------------------
// Launch
// ---------------------------------------------------------------------------
extern "C" void kernel_launch(void* const* d_in, const int* in_sizes, int n_in,
                              void* d_out, int out_size)
{
    const float* x   = (const float*)d_in[0];
    const float* gsc = (const float*)d_in[1];
    const float* gbi = (const float*)d_in[2];
    const float* Wq  = (const float*)d_in[3];
    const float* bq  = (const float*)d_in[4];
    const float* Wk  = (const float*)d_in[5];
    const float* bk  = (const float*)d_in[6];
    const float* Wv  = (const float*)d_in[7];
    const float* bv  = (const float*)d_in[8];
    const float* Wo  = (const float*)d_in[9];
    const float* bo  = (const float*)d_in[10];
    float* out = (float*)d_out;

    float *ft, *q, *k, *v, *lg, *at;
    cudaGetSymbolAddress((void**)&ft, g_ft);
    cudaGetSymbolAddress((void**)&q,  g_q);
    cudaGetSymbolAddress((void**)&k,  g_k);
    cudaGetSymbolAddress((void**)&v,  g_v);
    cudaGetSymbolAddress((void**)&lg, g_lg);
    cudaGetSymbolAddress((void**)&at, g_at);

    const long long sBSC = (long long)SS * CC;   // per-batch stride for q/k/v
    const long long sBSS = (long long)SS * SS;   // per-batch stride for logits

    // 1) GroupNorm
    gn_kernel<<<BB * GG, 256>>>(x, gsc, gbi, ft);

    // 2) Q/K/V projections: [32768,256] x [256,256]
    dim3 gproj(MS / 64, CC / 64, 1);
    sgemm64<0><<<gproj, 256>>>(ft, Wq, bq, nullptr, q, MS, CC, CC, 1.f, 0, 0, 0);
    sgemm64<0><<<gproj, 256>>>(ft, Wk, bk, nullptr, k, MS, CC, CC, 1.f, 0, 0, 0);
    sgemm64<0><<<gproj, 256>>>(ft, Wv, bv, nullptr, v, MS, CC, CC, 1.f, 0, 0, 0);

    // 3) logits = (1/16) * Q K^T per batch: [1024,256] x [1024,256]^T
    dim3 glog(SS / 64, SS / 64, BB);
    sgemm64<1><<<glog, 256>>>(q, k, nullptr, nullptr, lg,
                              SS, SS, CC, 0.0625f, sBSC, sBSC, sBSS);

    // 4) softmax over the 1024 keys per (batch, query)
    softmax_kernel<<<BB * SS, 256>>>(lg);

    // 5) attn = W V per batch: [1024,1024] x [1024,256]
    dim3 gav(SS / 64, CC / 64, BB);
    sgemm64<0><<<gav, 256>>>(lg, v, nullptr, nullptr, at,
                             SS, CC, SS, 1.f, sBSS, sBSC, sBSC);

    // 6) out = attn Wo + bo + x
    sgemm64<0><<<gproj, 256>>>(at, Wo, bo, x, out, MS, CC, CC, 1.f, 0, 0, 0);
}

// round 3
// speedup vs baseline: 3.0307x; 3.0307x over previous
#include <cuda_runtime.h>
#include <cstdint>
#include <cstddef>

// Problem constants
#define BB   32
#define HH   32
#define WW   32
#define CC   256
#define SS   (HH * WW)        // 1024
#define GG   32
#define CPG  (CC / GG)        // 8
#define MS   (BB * SS)        // 32768
#define EPS  1e-5f

// GEMM tile config
#define BM 128
#define BN 128
#define BK 32
#define ASTRIDE 36                       // padded k-stride (floats) -> conflict-free
#define A_SZ (BM * ASTRIDE)              // floats per A stage
#define B_SZ (BN * ASTRIDE)
#define STAGE_F (A_SZ + B_SZ)            // 9216 floats
#define SMEM_BYTES (2 * STAGE_F * 4)     // 73728 bytes

// ---------------------------------------------------------------------------
// Scratch
// ---------------------------------------------------------------------------
__device__ float g_ft  [(size_t)MS * CC];          // GN output (tf32-rounded)
__device__ float g_qkv [(size_t)MS * 3 * CC];      // fused Q|K|V, row stride 768
__device__ float g_vt  [(size_t)BB * CC * SS];     // V^T per batch [c][s]
__device__ float g_lg  [(size_t)BB * SS * SS];     // logits / probs
__device__ float g_at  [(size_t)MS * CC];          // attention out (pre-Wo)
__device__ float g_wt  [4 * CC * CC];              // Wq^T|Wk^T|Wv^T|Wo^T (rounded)
__device__ float g_bqkv[3 * CC];                   // packed biases

// ---------------------------------------------------------------------------
// Helpers
// ---------------------------------------------------------------------------
__device__ __forceinline__ uint32_t smem_u32(const void* p) {
    uint32_t a;
    asm("{ .reg .u64 t; cvta.to.shared.u64 t, %1; cvt.u32.u64 %0, t; }" : "=r"(a) : "l"(p));
    return a;
}
__device__ __forceinline__ float tf32r(float x) {
    uint32_t u;
    asm("cvt.rna.tf32.f32 %0, %1;" : "=r"(u) : "f"(x));
    return __uint_as_float(u);
}
__device__ __forceinline__ void cp16(uint32_t s, const float* g) {
    asm volatile("cp.async.cg.shared.global [%0], [%1], 16;" :: "r"(s), "l"(g));
}
__device__ __forceinline__ void mma_tf32(float* d,
                                         uint32_t a0, uint32_t a1, uint32_t a2, uint32_t a3,
                                         uint32_t b0, uint32_t b1) {
    asm volatile(
        "mma.sync.aligned.m16n8k8.row.col.f32.tf32.tf32.f32 "
        "{%0,%1,%2,%3}, {%4,%5,%6,%7}, {%8,%9}, {%0,%1,%2,%3};"
        : "+f"(d[0]), "+f"(d[1]), "+f"(d[2]), "+f"(d[3])
        : "r"(a0), "r"(a1), "r"(a2), "r"(a3), "r"(b0), "r"(b1));
}

// ---------------------------------------------------------------------------
// GroupNorm: one block per (batch, group), output tf32-rounded.
// ---------------------------------------------------------------------------
__global__ void gn_kernel(const float* __restrict__ x,
                          const float* __restrict__ scale,
                          const float* __restrict__ bias)
{
    const int b = blockIdx.x / GG, g = blockIdx.x % GG, tid = threadIdx.x;
    const float* xb = x + (size_t)b * SS * CC + g * CPG;

    float sum = 0.f, ssq = 0.f;
#pragma unroll
    for (int kk = 0; kk < 4; kk++) {
        const int s = tid + kk * 256;
        const float4* p = (const float4*)(xb + (size_t)s * CC);
        float4 a = p[0], c = p[1];
        sum += a.x + a.y + a.z + a.w + c.x + c.y + c.z + c.w;
        ssq += a.x*a.x + a.y*a.y + a.z*a.z + a.w*a.w
             + c.x*c.x + c.y*c.y + c.z*c.z + c.w*c.w;
    }
    __shared__ float r0[256], r1[256];
    r0[tid] = sum; r1[tid] = ssq;
    __syncthreads();
    for (int off = 128; off > 0; off >>= 1) {
        if (tid < off) { r0[tid] += r0[tid + off]; r1[tid] += r1[tid + off]; }
        __syncthreads();
    }
    const float mean = r0[0] * (1.f / 8192.f);
    const float var  = r1[0] * (1.f / 8192.f) - mean * mean;
    const float inv  = rsqrtf(var + EPS);

    float sc[CPG], bi[CPG];
#pragma unroll
    for (int c = 0; c < CPG; c++) {
        sc[c] = scale[g * CPG + c] * inv;
        bi[c] = bias [g * CPG + c];
    }
    float* fb = g_ft + (size_t)b * SS * CC + g * CPG;
#pragma unroll
    for (int kk = 0; kk < 4; kk++) {
        const int s = tid + kk * 256;
        const float* xi = xb + (size_t)s * CC;
        float*       fo = fb + (size_t)s * CC;
#pragma unroll
        for (int c = 0; c < CPG; c++)
            fo[c] = tf32r((xi[c] - mean) * sc[c] + bi[c]);
    }
}

// ---------------------------------------------------------------------------
// Weight transpose (+tf32 round): g_wt[i][n*256+k] = W_i[k*256+n]
// ---------------------------------------------------------------------------
__global__ void transpose_w(const float* __restrict__ Wq, const float* __restrict__ Wk,
                            const float* __restrict__ Wv, const float* __restrict__ Wo)
{
    __shared__ float t[32][33];
    const int i = blockIdx.z;
    const float* W = (i == 0) ? Wq : (i == 1) ? Wk : (i == 2) ? Wv : Wo;
    const int kb = blockIdx.x * 32, nb = blockIdx.y * 32;
    const int tx = threadIdx.x, ty = threadIdx.y;
#pragma unroll
    for (int j = 0; j < 4; j++)
        t[ty + j * 8][tx] = W[(size_t)(kb + ty + j * 8) * CC + nb + tx];
    __syncthreads();
    float* out = g_wt + (size_t)i * CC * CC;
#pragma unroll
    for (int j = 0; j < 4; j++)
        out[(size_t)(nb + ty + j * 8) * CC + kb + tx] = tf32r(t[tx][ty + j * 8]);
}

__global__ void pack_bias(const float* __restrict__ bq, const float* __restrict__ bk,
                          const float* __restrict__ bv)
{
    const int i = threadIdx.x;            // 256 threads
    g_bqkv[i]           = bq[i];
    g_bqkv[i + CC]      = bk[i];
    g_bqkv[i + 2 * CC]  = bv[i];
}

// ---------------------------------------------------------------------------
// V transpose: g_vt[b][c][s] = g_qkv[b*SS + s][512 + c]  (already rounded)
// ---------------------------------------------------------------------------
__global__ void transpose_v()
{
    __shared__ float t[32][33];
    const int b = blockIdx.z;
    const int sb = blockIdx.x * 32, cb = blockIdx.y * 32;
    const int tx = threadIdx.x, ty = threadIdx.y;
    const float* v = g_qkv + (size_t)b * SS * 3 * CC + 2 * CC;
    float* vt = g_vt + (size_t)b * CC * SS;
#pragma unroll
    for (int j = 0; j < 4; j++)
        t[ty + j * 8][tx] = v[(size_t)(sb + ty + j * 8) * (3 * CC) + cb + tx];
    __syncthreads();
#pragma unroll
    for (int j = 0; j < 4; j++)
        vt[(size_t)(cb + ty + j * 8) * SS + sb + tx] = t[tx][ty + j * 8];
}

// ---------------------------------------------------------------------------
// tf32 tensor-core GEMM: C[m,n] = alpha * sum_k A[m,k]*B[n,k] (+bias)(+resid)
// A:[M,K] lda, B:[N,K] ldb (both K-major, tf32-prerounded), C ldc.
// 128x128x32 tiles, cp.async double buffer, mma.sync m16n8k8.
// ---------------------------------------------------------------------------
__global__ void __launch_bounds__(256)
mma_gemm(const float* __restrict__ A, const float* __restrict__ B,
         const float* __restrict__ bias, const float* __restrict__ resid,
         float* __restrict__ C,
         int K, int lda, int ldb, int ldc,
         float alpha, int round_out,
         long long sA, long long sB, long long sC)
{
    extern __shared__ float sm[];
    const int batch = blockIdx.z;
    A += (size_t)batch * sA;
    B += (size_t)batch * sB;
    C += (size_t)batch * sC;
    if (resid) resid += (size_t)batch * sC;

    const int tid  = threadIdx.x;
    const int lane = tid & 31;
    const int wid  = tid >> 5;
    const int warp_m = wid & 3;           // 4 warps over M (32 rows each)
    const int warp_n = wid >> 2;          // 2 warps over N (64 cols each)
    const int row0 = blockIdx.x * BM;
    const int col0 = blockIdx.y * BN;

    const float* Ab = A + (size_t)row0 * lda;
    const float* Bb = B + (size_t)col0 * ldb;
    const uint32_t sbase = smem_u32(sm);

    const int ldr = tid >> 3;             // base row for loads (x4 iters)
    const int ldc4 = (tid & 7) * 4;       // k-offset (floats)

    // issue cp.async for one stage (A tile + B tile), then commit
    auto load_stage = [&](int k0, int st) {
        const uint32_t abase = sbase + st * (STAGE_F * 4);
        const uint32_t bbase = abase + A_SZ * 4;
#pragma unroll
        for (int i = 0; i < 4; i++) {
            const int r = ldr + i * 32;
            cp16(abase + (r * ASTRIDE + ldc4) * 4, Ab + (size_t)r * lda + k0 + ldc4);
        }
#pragma unroll
        for (int i = 0; i < 4; i++) {
            const int r = ldr + i * 32;
            cp16(bbase + (r * ASTRIDE + ldc4) * 4, Bb + (size_t)r * ldb + k0 + ldc4);
        }
        asm volatile("cp.async.commit_group;" ::: "memory");
    };

    float acc[2][8][4];
#pragma unroll
    for (int a = 0; a < 2; a++)
#pragma unroll
        for (int b = 0; b < 8; b++)
#pragma unroll
            for (int c = 0; c < 4; c++) acc[a][b][c] = 0.f;

    const int nk = K / BK;
    load_stage(0, 0);

    const int g  = lane >> 2;             // 0..7
    const int tg = lane & 3;              // 0..3

    for (int t = 0; t < nk; t++) {
        if (t + 1 < nk) {
            load_stage((t + 1) * BK, (t + 1) & 1);
            asm volatile("cp.async.wait_group 1;" ::: "memory");
        } else {
            asm volatile("cp.async.wait_group 0;" ::: "memory");
        }
        __syncthreads();

        const float* sA_ = sm + (t & 1) * STAGE_F;
        const float* sB_ = sA_ + A_SZ;

#pragma unroll
        for (int ks = 0; ks < 4; ks++) {
            const int k = ks * 8;
            uint32_t a[2][4];
#pragma unroll
            for (int mt = 0; mt < 2; mt++) {
                const int rm = warp_m * 32 + mt * 16 + g;
                const float* p = sA_ + rm * ASTRIDE + k + tg;
                a[mt][0] = __float_as_uint(p[0]);
                a[mt][1] = __float_as_uint(p[8 * ASTRIDE]);
                a[mt][2] = __float_as_uint(p[4]);
                a[mt][3] = __float_as_uint(p[8 * ASTRIDE + 4]);
            }
#pragma unroll
            for (int nt = 0; nt < 8; nt++) {
                const int n = warp_n * 64 + nt * 8 + g;
                const float* p = sB_ + n * ASTRIDE + k + tg;
                const uint32_t b0 = __float_as_uint(p[0]);
                const uint32_t b1 = __float_as_uint(p[4]);
                mma_tf32(acc[0][nt], a[0][0], a[0][1], a[0][2], a[0][3], b0, b1);
                mma_tf32(acc[1][nt], a[1][0], a[1][1], a[1][2], a[1][3], b0, b1);
            }
        }
        __syncthreads();
    }

    // Epilogue
#pragma unroll
    for (int mt = 0; mt < 2; mt++) {
#pragma unroll
        for (int half = 0; half < 2; half++) {
            const int r = row0 + warp_m * 32 + mt * 16 + half * 8 + g;
            float* Crow = C + (size_t)r * ldc;
            const float* Rrow = resid ? resid + (size_t)r * ldc : nullptr;
#pragma unroll
            for (int nt = 0; nt < 8; nt++) {
                const int cix = col0 + warp_n * 64 + nt * 8 + tg * 2;
                float v0 = acc[mt][nt][half * 2 + 0] * alpha;
                float v1 = acc[mt][nt][half * 2 + 1] * alpha;
                if (bias) { v0 += bias[cix]; v1 += bias[cix + 1]; }
                if (Rrow) { v0 += Rrow[cix]; v1 += Rrow[cix + 1]; }
                if (round_out) { v0 = tf32r(v0); v1 = tf32r(v1); }
                *(float2*)&Crow[cix] = make_float2(v0, v1);
            }
        }
    }
}

// ---------------------------------------------------------------------------
// Row softmax over 1024 cols; output tf32-rounded (feeds attn GEMM).
// ---------------------------------------------------------------------------
__global__ void softmax_kernel(float* __restrict__ lg)
{
    const size_t row = blockIdx.x;
    float4* p = (float4*)(lg + row * (size_t)SS);
    const int tid = threadIdx.x;

    float4 v = p[tid];
    float m = fmaxf(fmaxf(v.x, v.y), fmaxf(v.z, v.w));
    __shared__ float red[256];
    red[tid] = m;
    __syncthreads();
    for (int off = 128; off > 0; off >>= 1) {
        if (tid < off) red[tid] = fmaxf(red[tid], red[tid + off]);
        __syncthreads();
    }
    m = red[0];
    __syncthreads();
    v.x = expf(v.x - m); v.y = expf(v.y - m);
    v.z = expf(v.z - m); v.w = expf(v.w - m);
    float s = v.x + v.y + v.z + v.w;
    red[tid] = s;
    __syncthreads();
    for (int off = 128; off > 0; off >>= 1) {
        if (tid < off) red[tid] += red[tid + off];
        __syncthreads();
    }
    const float inv = 1.f / red[0];
    v.x = tf32r(v.x * inv); v.y = tf32r(v.y * inv);
    v.z = tf32r(v.z * inv); v.w = tf32r(v.w * inv);
    p[tid] = v;
}

// ---------------------------------------------------------------------------
// Launch
// ---------------------------------------------------------------------------
extern "C" void kernel_launch(void* const* d_in, const int* in_sizes, int n_in,
                              void* d_out, int out_size)
{
    const float* x   = (const float*)d_in[0];
    const float* gsc = (const float*)d_in[1];
    const float* gbi = (const float*)d_in[2];
    const float* Wq  = (const float*)d_in[3];
    const float* bq  = (const float*)d_in[4];
    const float* Wk  = (const float*)d_in[5];
    const float* bk  = (const float*)d_in[6];
    const float* Wv  = (const float*)d_in[7];
    const float* bv  = (const float*)d_in[8];
    const float* Wo  = (const float*)d_in[9];
    const float* bo  = (const float*)d_in[10];
    float* out = (float*)d_out;

    cudaFuncSetAttribute(mma_gemm, cudaFuncAttributeMaxDynamicSharedMemorySize,
                         SMEM_BYTES);

    float *ft, *qkv, *vt, *lg, *at, *wt, *bqkv;
    cudaGetSymbolAddress((void**)&ft,   g_ft);
    cudaGetSymbolAddress((void**)&qkv,  g_qkv);
    cudaGetSymbolAddress((void**)&vt,   g_vt);
    cudaGetSymbolAddress((void**)&lg,   g_lg);
    cudaGetSymbolAddress((void**)&at,   g_at);
    cudaGetSymbolAddress((void**)&wt,   g_wt);
    cudaGetSymbolAddress((void**)&bqkv, g_bqkv);

    const long long sQKV = (long long)SS * 3 * CC;
    const long long sBSS = (long long)SS * SS;
    const long long sVT  = (long long)CC * SS;
    const long long sBSC = (long long)SS * CC;

    // 1) GroupNorm, weight transpose, bias pack
    gn_kernel<<<BB * GG, 256>>>(x, gsc, gbi);
    transpose_w<<<dim3(8, 8, 4), dim3(32, 8)>>>(Wq, Wk, Wv, Wo);
    pack_bias<<<1, 256>>>(bq, bk, bv);

    // 2) fused QKV projection: [32768,256] x [768,256]^T -> [32768,768]
    mma_gemm<<<dim3(MS / BM, (3 * CC) / BN, 1), 256, SMEM_BYTES>>>(
        ft, wt, bqkv, nullptr, qkv,
        CC, CC, CC, 3 * CC, 1.f, 1, 0, 0, 0);

    // 3) logits = (1/16) Q K^T per batch: [1024,256]x[1024,256]^T
    mma_gemm<<<dim3(SS / BM, SS / BN, BB), 256, SMEM_BYTES>>>(
        qkv + 0, qkv + CC, nullptr, nullptr, lg,
        CC, 3 * CC, 3 * CC, SS, 0.0625f, 0, sQKV, sQKV, sBSS);

    // 4) V transpose + softmax
    transpose_v<<<dim3(SS / 32, CC / 32, BB), dim3(32, 8)>>>();
    softmax_kernel<<<BB * SS, 256>>>(lg);

    // 5) attn = P V per batch: [1024,1024] x [256,1024]^T
    mma_gemm<<<dim3(SS / BM, CC / BN, BB), 256, SMEM_BYTES>>>(
        lg, vt, nullptr, nullptr, at,
        SS, SS, SS, CC, 1.f, 1, sBSS, sVT, sBSC);

    // 6) out = attn Wo + bo + x
    mma_gemm<<<dim3(MS / BM, CC / BN, 1), 256, SMEM_BYTES>>>(
        at, wt + 3 * CC * CC, bo, x, out,
        CC, CC, CC, CC, 1.f, 0, 0, 0, 0);
}

// round 4
// speedup vs baseline: 3.0772x; 1.0153x over previous
#include <cuda_runtime.h>
#include <cstdint>
#include <cstddef>

// Problem constants
#define BB   32
#define HH   32
#define WW   32
#define CC   256
#define SS   (HH * WW)        // 1024
#define GG   32
#define CPG  (CC / GG)        // 8
#define MS   (BB * SS)        // 32768
#define EPS  1e-5f

// GEMM tile config
#define BM 128
#define BN 128
#define BK 32
#define NSTAGE 3
#define ASTRIDE 36                       // padded k-stride (floats) -> conflict-free
#define A_SZ (BM * ASTRIDE)
#define B_SZ (BN * ASTRIDE)
#define STAGE_F (A_SZ + B_SZ)            // 9216 floats / stage
#define SMEM_BYTES (NSTAGE * STAGE_F * 4)  // 110592 bytes

// ---------------------------------------------------------------------------
// Scratch
// ---------------------------------------------------------------------------
__device__ float g_ft  [(size_t)MS * CC];
__device__ float g_qkv [(size_t)MS * 3 * CC];
__device__ float g_vt  [(size_t)BB * CC * SS];
__device__ float g_lg  [(size_t)BB * SS * SS];
__device__ float g_at  [(size_t)MS * CC];
__device__ float g_wt  [4 * CC * CC];
__device__ float g_bqkv[3 * CC];

// ---------------------------------------------------------------------------
// Helpers
// ---------------------------------------------------------------------------
__device__ __forceinline__ uint32_t smem_u32(const void* p) {
    uint32_t a;
    asm("{ .reg .u64 t; cvta.to.shared.u64 t, %1; cvt.u32.u64 %0, t; }" : "=r"(a) : "l"(p));
    return a;
}
__device__ __forceinline__ float tf32r(float x) {
    uint32_t u;
    asm("cvt.rna.tf32.f32 %0, %1;" : "=r"(u) : "f"(x));
    return __uint_as_float(u);
}
__device__ __forceinline__ void cp16(uint32_t s, const float* g) {
    asm volatile("cp.async.cg.shared.global [%0], [%1], 16;" :: "r"(s), "l"(g));
}
__device__ __forceinline__ void mma_tf32(float* d,
                                         uint32_t a0, uint32_t a1, uint32_t a2, uint32_t a3,
                                         uint32_t b0, uint32_t b1) {
    asm volatile(
        "mma.sync.aligned.m16n8k8.row.col.f32.tf32.tf32.f32 "
        "{%0,%1,%2,%3}, {%4,%5,%6,%7}, {%8,%9}, {%0,%1,%2,%3};"
        : "+f"(d[0]), "+f"(d[1]), "+f"(d[2]), "+f"(d[3])
        : "r"(a0), "r"(a1), "r"(a2), "r"(a3), "r"(b0), "r"(b1));
}

// ---------------------------------------------------------------------------
// GroupNorm (tf32-rounded output)
// ---------------------------------------------------------------------------
__global__ void gn_kernel(const float* __restrict__ x,
                          const float* __restrict__ scale,
                          const float* __restrict__ bias)
{
    const int b = blockIdx.x / GG, g = blockIdx.x % GG, tid = threadIdx.x;
    const float* xb = x + (size_t)b * SS * CC + g * CPG;

    float sum = 0.f, ssq = 0.f;
#pragma unroll
    for (int kk = 0; kk < 4; kk++) {
        const int s = tid + kk * 256;
        const float4* p = (const float4*)(xb + (size_t)s * CC);
        float4 a = p[0], c = p[1];
        sum += a.x + a.y + a.z + a.w + c.x + c.y + c.z + c.w;
        ssq += a.x*a.x + a.y*a.y + a.z*a.z + a.w*a.w
             + c.x*c.x + c.y*c.y + c.z*c.z + c.w*c.w;
    }
    __shared__ float r0[256], r1[256];
    r0[tid] = sum; r1[tid] = ssq;
    __syncthreads();
    for (int off = 128; off > 0; off >>= 1) {
        if (tid < off) { r0[tid] += r0[tid + off]; r1[tid] += r1[tid + off]; }
        __syncthreads();
    }
    const float mean = r0[0] * (1.f / 8192.f);
    const float var  = r1[0] * (1.f / 8192.f) - mean * mean;
    const float inv  = rsqrtf(var + EPS);

    float sc[CPG], bi[CPG];
#pragma unroll
    for (int c = 0; c < CPG; c++) {
        sc[c] = scale[g * CPG + c] * inv;
        bi[c] = bias [g * CPG + c];
    }
    float* fb = g_ft + (size_t)b * SS * CC + g * CPG;
#pragma unroll
    for (int kk = 0; kk < 4; kk++) {
        const int s = tid + kk * 256;
        const float* xi = xb + (size_t)s * CC;
        float*       fo = fb + (size_t)s * CC;
#pragma unroll
        for (int c = 0; c < CPG; c++)
            fo[c] = tf32r((xi[c] - mean) * sc[c] + bi[c]);
    }
}

// ---------------------------------------------------------------------------
// Weight transpose (+tf32 round)
// ---------------------------------------------------------------------------
__global__ void transpose_w(const float* __restrict__ Wq, const float* __restrict__ Wk,
                            const float* __restrict__ Wv, const float* __restrict__ Wo)
{
    __shared__ float t[32][33];
    const int i = blockIdx.z;
    const float* W = (i == 0) ? Wq : (i == 1) ? Wk : (i == 2) ? Wv : Wo;
    const int kb = blockIdx.x * 32, nb = blockIdx.y * 32;
    const int tx = threadIdx.x, ty = threadIdx.y;
#pragma unroll
    for (int j = 0; j < 4; j++)
        t[ty + j * 8][tx] = W[(size_t)(kb + ty + j * 8) * CC + nb + tx];
    __syncthreads();
    float* out = g_wt + (size_t)i * CC * CC;
#pragma unroll
    for (int j = 0; j < 4; j++)
        out[(size_t)(nb + ty + j * 8) * CC + kb + tx] = tf32r(t[tx][ty + j * 8]);
}

__global__ void pack_bias(const float* __restrict__ bq, const float* __restrict__ bk,
                          const float* __restrict__ bv)
{
    const int i = threadIdx.x;
    g_bqkv[i]          = bq[i];
    g_bqkv[i + CC]     = bk[i];
    g_bqkv[i + 2 * CC] = bv[i];
}

// ---------------------------------------------------------------------------
// V transpose: g_vt[b][c][s] = g_qkv[b*SS + s][512 + c]
// ---------------------------------------------------------------------------
__global__ void transpose_v()
{
    __shared__ float t[32][33];
    const int b = blockIdx.z;
    const int sb = blockIdx.x * 32, cb = blockIdx.y * 32;
    const int tx = threadIdx.x, ty = threadIdx.y;
    const float* v = g_qkv + (size_t)b * SS * 3 * CC + 2 * CC;
    float* vt = g_vt + (size_t)b * CC * SS;
#pragma unroll
    for (int j = 0; j < 4; j++)
        t[ty + j * 8][tx] = v[(size_t)(sb + ty + j * 8) * (3 * CC) + cb + tx];
    __syncthreads();
#pragma unroll
    for (int j = 0; j < 4; j++)
        vt[(size_t)(cb + ty + j * 8) * SS + sb + tx] = t[tx][ty + j * 8];
}

// ---------------------------------------------------------------------------
// tf32 tensor-core GEMM (3-stage cp.async ring, 1 barrier/iter)
// C[m,n] = alpha * sum_k A[m,k]*B[n,k] (+bias)(+resid)
// swapxy: if 1, blockIdx.y indexes M tiles and blockIdx.x indexes N tiles.
// ---------------------------------------------------------------------------
__global__ void __launch_bounds__(256, 2)
mma_gemm(const float* __restrict__ A, const float* __restrict__ B,
         const float* __restrict__ bias, const float* __restrict__ resid,
         float* __restrict__ C,
         int K, int lda, int ldb, int ldc,
         float alpha, int round_out, int swapxy,
         long long sA, long long sB, long long sC)
{
    extern __shared__ float sm[];
    const int batch = blockIdx.z;
    A += (size_t)batch * sA;
    B += (size_t)batch * sB;
    C += (size_t)batch * sC;
    if (resid) resid += (size_t)batch * sC;

    const int tid  = threadIdx.x;
    const int lane = tid & 31;
    const int wid  = tid >> 5;
    const int warp_m = wid & 3;
    const int warp_n = wid >> 2;
    const int bx = swapxy ? blockIdx.y : blockIdx.x;
    const int by = swapxy ? blockIdx.x : blockIdx.y;
    const int row0 = bx * BM;
    const int col0 = by * BN;

    const float* Ab = A + (size_t)row0 * lda;
    const float* Bb = B + (size_t)col0 * ldb;
    const uint32_t sbase = smem_u32(sm);

    const int ldr  = tid >> 3;
    const int ldc4 = (tid & 7) * 4;

    auto load_stage = [&](int k0, int st) {
        const uint32_t abase = sbase + st * (STAGE_F * 4);
        const uint32_t bbase = abase + A_SZ * 4;
#pragma unroll
        for (int i = 0; i < 4; i++) {
            const int r = ldr + i * 32;
            cp16(abase + (r * ASTRIDE + ldc4) * 4, Ab + (size_t)r * lda + k0 + ldc4);
        }
#pragma unroll
        for (int i = 0; i < 4; i++) {
            const int r = ldr + i * 32;
            cp16(bbase + (r * ASTRIDE + ldc4) * 4, Bb + (size_t)r * ldb + k0 + ldc4);
        }
        asm volatile("cp.async.commit_group;" ::: "memory");
    };

    float acc[2][8][4];
#pragma unroll
    for (int a = 0; a < 2; a++)
#pragma unroll
        for (int b = 0; b < 8; b++)
#pragma unroll
            for (int c = 0; c < 4; c++) acc[a][b][c] = 0.f;

    const int nk = K / BK;          // >= 8 for all shapes here
    load_stage(0, 0);
    load_stage(BK, 1);

    const int g  = lane >> 2;
    const int tg = lane & 3;

    int st = 0;                     // ring index = t % 3
    for (int t = 0; t < nk; t++) {
        if (t + 1 < nk) asm volatile("cp.async.wait_group 1;" ::: "memory");
        else            asm volatile("cp.async.wait_group 0;" ::: "memory");
        __syncthreads();

        if (t + 2 < nk) {
            int st2 = st + 2; if (st2 >= NSTAGE) st2 -= NSTAGE;
            load_stage((t + 2) * BK, st2);
        }

        const float* sA_ = sm + st * STAGE_F;
        const float* sB_ = sA_ + A_SZ;

#pragma unroll
        for (int ks = 0; ks < 4; ks++) {
            const int k = ks * 8;
            uint32_t a[2][4];
#pragma unroll
            for (int mt = 0; mt < 2; mt++) {
                const int rm = warp_m * 32 + mt * 16 + g;
                const float* p = sA_ + rm * ASTRIDE + k + tg;
                a[mt][0] = __float_as_uint(p[0]);
                a[mt][1] = __float_as_uint(p[8 * ASTRIDE]);
                a[mt][2] = __float_as_uint(p[4]);
                a[mt][3] = __float_as_uint(p[8 * ASTRIDE + 4]);
            }
#pragma unroll
            for (int nt = 0; nt < 8; nt++) {
                const int n = warp_n * 64 + nt * 8 + g;
                const float* p = sB_ + n * ASTRIDE + k + tg;
                const uint32_t b0 = __float_as_uint(p[0]);
                const uint32_t b1 = __float_as_uint(p[4]);
                mma_tf32(acc[0][nt], a[0][0], a[0][1], a[0][2], a[0][3], b0, b1);
                mma_tf32(acc[1][nt], a[1][0], a[1][1], a[1][2], a[1][3], b0, b1);
            }
        }
        st++; if (st >= NSTAGE) st -= NSTAGE;
    }

    // Epilogue
#pragma unroll
    for (int mt = 0; mt < 2; mt++) {
#pragma unroll
        for (int half = 0; half < 2; half++) {
            const int r = row0 + warp_m * 32 + mt * 16 + half * 8 + g;
            float* Crow = C + (size_t)r * ldc;
            const float* Rrow = resid ? resid + (size_t)r * ldc : nullptr;
#pragma unroll
            for (int nt = 0; nt < 8; nt++) {
                const int cix = col0 + warp_n * 64 + nt * 8 + tg * 2;
                float v0 = acc[mt][nt][half * 2 + 0] * alpha;
                float v1 = acc[mt][nt][half * 2 + 1] * alpha;
                if (bias) { v0 += bias[cix]; v1 += bias[cix + 1]; }
                if (Rrow) { v0 += Rrow[cix]; v1 += Rrow[cix + 1]; }
                if (round_out) { v0 = tf32r(v0); v1 = tf32r(v1); }
                *(float2*)&Crow[cix] = make_float2(v0, v1);
            }
        }
    }
}

// ---------------------------------------------------------------------------
// Row softmax over 1024 cols; tf32-rounded output.
// ---------------------------------------------------------------------------
__global__ void softmax_kernel(float* __restrict__ lg)
{
    const size_t row = blockIdx.x;
    float4* p = (float4*)(lg + row * (size_t)SS);
    const int tid = threadIdx.x;

    float4 v = p[tid];
    float m = fmaxf(fmaxf(v.x, v.y), fmaxf(v.z, v.w));
    __shared__ float red[256];
    red[tid] = m;
    __syncthreads();
    for (int off = 128; off > 0; off >>= 1) {
        if (tid < off) red[tid] = fmaxf(red[tid], red[tid + off]);
        __syncthreads();
    }
    m = red[0];
    __syncthreads();
    v.x = expf(v.x - m); v.y = expf(v.y - m);
    v.z = expf(v.z - m); v.w = expf(v.w - m);
    float s = v.x + v.y + v.z + v.w;
    red[tid] = s;
    __syncthreads();
    for (int off = 128; off > 0; off >>= 1) {
        if (tid < off) red[tid] += red[tid + off];
        __syncthreads();
    }
    const float inv = 1.f / red[0];
    v.x = tf32r(v.x * inv); v.y = tf32r(v.y * inv);
    v.z = tf32r(v.z * inv); v.w = tf32r(v.w * inv);
    p[tid] = v;
}

// ---------------------------------------------------------------------------
// Launch
// ---------------------------------------------------------------------------
extern "C" void kernel_launch(void* const* d_in, const int* in_sizes, int n_in,
                              void* d_out, int out_size)
{
    const float* x   = (const float*)d_in[0];
    const float* gsc = (const float*)d_in[1];
    const float* gbi = (const float*)d_in[2];
    const float* Wq  = (const float*)d_in[3];
    const float* bq  = (const float*)d_in[4];
    const float* Wk  = (const float*)d_in[5];
    const float* bk  = (const float*)d_in[6];
    const float* Wv  = (const float*)d_in[7];
    const float* bv  = (const float*)d_in[8];
    const float* Wo  = (const float*)d_in[9];
    const float* bo  = (const float*)d_in[10];
    float* out = (float*)d_out;

    cudaFuncSetAttribute(mma_gemm, cudaFuncAttributeMaxDynamicSharedMemorySize,
                         SMEM_BYTES);

    float *ft, *qkv, *vt, *lg, *at, *wt, *bqkv;
    cudaGetSymbolAddress((void**)&ft,   g_ft);
    cudaGetSymbolAddress((void**)&qkv,  g_qkv);
    cudaGetSymbolAddress((void**)&vt,   g_vt);
    cudaGetSymbolAddress((void**)&lg,   g_lg);
    cudaGetSymbolAddress((void**)&at,   g_at);
    cudaGetSymbolAddress((void**)&wt,   g_wt);
    cudaGetSymbolAddress((void**)&bqkv, g_bqkv);

    const long long sQKV = (long long)SS * 3 * CC;
    const long long sBSS = (long long)SS * SS;
    const long long sVT  = (long long)CC * SS;
    const long long sBSC = (long long)SS * CC;

    // 1) GroupNorm, weight transpose, bias pack
    gn_kernel<<<BB * GG, 256>>>(x, gsc, gbi);
    transpose_w<<<dim3(8, 8, 4), dim3(32, 8)>>>(Wq, Wk, Wv, Wo);
    pack_bias<<<1, 256>>>(bq, bk, bv);

    // 2) fused QKV projection (grid: N tiles fastest for L2 reuse of A)
    mma_gemm<<<dim3((3 * CC) / BN, MS / BM, 1), 256, SMEM_BYTES>>>(
        ft, wt, bqkv, nullptr, qkv,
        CC, CC, CC, 3 * CC, 1.f, 1, 1, 0, 0, 0);

    // 3) logits = (1/16) Q K^T per batch
    mma_gemm<<<dim3(SS / BM, SS / BN, BB), 256, SMEM_BYTES>>>(
        qkv + 0, qkv + CC, nullptr, nullptr, lg,
        CC, 3 * CC, 3 * CC, SS, 0.0625f, 0, 0, sQKV, sQKV, sBSS);

    // 4) V transpose + softmax
    transpose_v<<<dim3(SS / 32, CC / 32, BB), dim3(32, 8)>>>();
    softmax_kernel<<<BB * SS, 256>>>(lg);

    // 5) attn = P V per batch
    mma_gemm<<<dim3(SS / BM, CC / BN, BB), 256, SMEM_BYTES>>>(
        lg, vt, nullptr, nullptr, at,
        SS, SS, SS, CC, 1.f, 1, 0, sBSS, sVT, sBSC);

    // 6) out = attn Wo + bo + x
    mma_gemm<<<dim3(CC / BN, MS / BM, 1), 256, SMEM_BYTES>>>(
        at, wt + 3 * CC * CC, bo, x, out,
        CC, CC, CC, CC, 1.f, 0, 1, 0, 0, 0);
}

// round 5
// speedup vs baseline: 4.8947x; 1.5906x over previous
#include <cuda_runtime.h>
#include <cuda_fp16.h>
#include <cstdint>
#include <cstddef>

// Problem constants
#define BB   32
#define HH   32
#define WW   32
#define CC   256
#define SS   (HH * WW)        // 1024
#define GG   32
#define CPG  (CC / GG)        // 8
#define MS   (BB * SS)        // 32768
#define EPS  1e-5f

// GEMM tile config (fp16 operands, fp32 accum)
#define BM 128
#define BN 128
#define BK 64                             // halves per K-tile (128 bytes/row)
#define NSTAGE 3
#define RS 72                             // padded row stride in halves
#define A_SZH (BM * RS)                   // halves per A stage
#define B_SZH (BN * RS)
#define STAGE_H (A_SZH + B_SZH)           // 18432 halves / stage
#define SMEM_BYTES (NSTAGE * STAGE_H * 2) // 110592 bytes

// ---------------------------------------------------------------------------
// Scratch
// ---------------------------------------------------------------------------
__device__ __half g_ft  [(size_t)MS * CC];          // GN output (fp16)
__device__ __half g_qkv [(size_t)MS * 3 * CC];      // Q|K|V rows (stride 768)
__device__ __half g_vt  [(size_t)BB * CC * SS];     // V^T per batch
__device__ float  g_lg  [(size_t)BB * SS * SS];     // logits (fp32)
__device__ __half g_p   [(size_t)BB * SS * SS];     // softmax probs (fp16)
__device__ __half g_at  [(size_t)MS * CC];          // attn out (fp16)
__device__ __half g_wt  [4 * CC * CC];              // W^T (fp16)
__device__ float  g_bqkv[3 * CC];

// ---------------------------------------------------------------------------
// Helpers
// ---------------------------------------------------------------------------
__device__ __forceinline__ uint32_t smem_u32(const void* p) {
    uint32_t a;
    asm("{ .reg .u64 t; cvta.to.shared.u64 t, %1; cvt.u32.u64 %0, t; }" : "=r"(a) : "l"(p));
    return a;
}
__device__ __forceinline__ void cp16(uint32_t s, const void* g) {
    asm volatile("cp.async.cg.shared.global [%0], [%1], 16;" :: "r"(s), "l"(g));
}
__device__ __forceinline__ void mma_f16(float* d,
                                        uint32_t a0, uint32_t a1, uint32_t a2, uint32_t a3,
                                        uint32_t b0, uint32_t b1) {
    asm volatile(
        "mma.sync.aligned.m16n8k16.row.col.f32.f16.f16.f32 "
        "{%0,%1,%2,%3}, {%4,%5,%6,%7}, {%8,%9}, {%0,%1,%2,%3};"
        : "+f"(d[0]), "+f"(d[1]), "+f"(d[2]), "+f"(d[3])
        : "r"(a0), "r"(a1), "r"(a2), "r"(a3), "r"(b0), "r"(b1));
}

// ---------------------------------------------------------------------------
// GroupNorm -> fp16
// ---------------------------------------------------------------------------
__global__ void gn_kernel(const float* __restrict__ x,
                          const float* __restrict__ scale,
                          const float* __restrict__ bias)
{
    const int b = blockIdx.x / GG, g = blockIdx.x % GG, tid = threadIdx.x;
    const float* xb = x + (size_t)b * SS * CC + g * CPG;

    float sum = 0.f, ssq = 0.f;
#pragma unroll
    for (int kk = 0; kk < 4; kk++) {
        const int s = tid + kk * 256;
        const float4* p = (const float4*)(xb + (size_t)s * CC);
        float4 a = p[0], c = p[1];
        sum += a.x + a.y + a.z + a.w + c.x + c.y + c.z + c.w;
        ssq += a.x*a.x + a.y*a.y + a.z*a.z + a.w*a.w
             + c.x*c.x + c.y*c.y + c.z*c.z + c.w*c.w;
    }
    __shared__ float r0[256], r1[256];
    r0[tid] = sum; r1[tid] = ssq;
    __syncthreads();
    for (int off = 128; off > 0; off >>= 1) {
        if (tid < off) { r0[tid] += r0[tid + off]; r1[tid] += r1[tid + off]; }
        __syncthreads();
    }
    const float mean = r0[0] * (1.f / 8192.f);
    const float var  = r1[0] * (1.f / 8192.f) - mean * mean;
    const float inv  = rsqrtf(var + EPS);

    float sc[CPG], bi[CPG];
#pragma unroll
    for (int c = 0; c < CPG; c++) {
        sc[c] = scale[g * CPG + c] * inv;
        bi[c] = bias [g * CPG + c];
    }
    __half* fb = g_ft + (size_t)b * SS * CC + g * CPG;
#pragma unroll
    for (int kk = 0; kk < 4; kk++) {
        const int s = tid + kk * 256;
        const float* xi = xb + (size_t)s * CC;
        __half2*    fo = (__half2*)(fb + (size_t)s * CC);
#pragma unroll
        for (int c = 0; c < 4; c++) {
            const float v0 = (xi[2*c]   - mean) * sc[2*c]   + bi[2*c];
            const float v1 = (xi[2*c+1] - mean) * sc[2*c+1] + bi[2*c+1];
            fo[c] = __floats2half2_rn(v0, v1);
        }
    }
}

// ---------------------------------------------------------------------------
// Weight transpose -> fp16:  g_wt[i][n*256+k] = (half)W_i[k*256+n]
// ---------------------------------------------------------------------------
__global__ void transpose_w(const float* __restrict__ Wq, const float* __restrict__ Wk,
                            const float* __restrict__ Wv, const float* __restrict__ Wo)
{
    __shared__ float t[32][33];
    const int i = blockIdx.z;
    const float* W = (i == 0) ? Wq : (i == 1) ? Wk : (i == 2) ? Wv : Wo;
    const int kb = blockIdx.x * 32, nb = blockIdx.y * 32;
    const int tx = threadIdx.x, ty = threadIdx.y;
#pragma unroll
    for (int j = 0; j < 4; j++)
        t[ty + j * 8][tx] = W[(size_t)(kb + ty + j * 8) * CC + nb + tx];
    __syncthreads();
    __half* out = g_wt + (size_t)i * CC * CC;
#pragma unroll
    for (int j = 0; j < 4; j++)
        out[(size_t)(nb + ty + j * 8) * CC + kb + tx] = __float2half_rn(t[tx][ty + j * 8]);
}

__global__ void pack_bias(const float* __restrict__ bq, const float* __restrict__ bk,
                          const float* __restrict__ bv)
{
    const int i = threadIdx.x;
    g_bqkv[i]          = bq[i];
    g_bqkv[i + CC]     = bk[i];
    g_bqkv[i + 2 * CC] = bv[i];
}

// ---------------------------------------------------------------------------
// V transpose (fp16): g_vt[b][c][s] = g_qkv[b*SS+s][512+c]
// ---------------------------------------------------------------------------
__global__ void transpose_v()
{
    __shared__ float t[32][33];
    const int b = blockIdx.z;
    const int sb = blockIdx.x * 32, cb = blockIdx.y * 32;
    const int tx = threadIdx.x, ty = threadIdx.y;
    const __half* v = g_qkv + (size_t)b * SS * 3 * CC + 2 * CC;
    __half* vt = g_vt + (size_t)b * CC * SS;
#pragma unroll
    for (int j = 0; j < 4; j++)
        t[ty + j * 8][tx] = __half2float(v[(size_t)(sb + ty + j * 8) * (3 * CC) + cb + tx]);
    __syncthreads();
#pragma unroll
    for (int j = 0; j < 4; j++)
        vt[(size_t)(cb + ty + j * 8) * SS + sb + tx] = __float2half_rn(t[tx][ty + j * 8]);
}

// ---------------------------------------------------------------------------
// fp16 tensor-core GEMM (3-stage cp.async ring)
// C[m,n] = alpha * sum_k A[m,k]*B[n,k] (+bias) (+resid)
// A:[M,K] lda halves; B:[N,K] ldb halves. Output: half (out_half) or float.
// ---------------------------------------------------------------------------
__global__ void __launch_bounds__(256, 2)
mma_gemm(const __half* __restrict__ A, const __half* __restrict__ B,
         const float* __restrict__ bias, const float* __restrict__ resid,
         void* __restrict__ Cvoid,
         int K, int lda, int ldb, int ldc,
         float alpha, int out_half, int swapxy,
         long long sA, long long sB, long long sC)
{
    extern __shared__ __half sm[];
    const int batch = blockIdx.z;
    A += (size_t)batch * sA;
    B += (size_t)batch * sB;

    const int tid  = threadIdx.x;
    const int lane = tid & 31;
    const int wid  = tid >> 5;
    const int warp_m = wid & 3;
    const int warp_n = wid >> 2;
    const int bx = swapxy ? blockIdx.y : blockIdx.x;
    const int by = swapxy ? blockIdx.x : blockIdx.y;
    const int row0 = bx * BM;
    const int col0 = by * BN;

    const __half* Ab = A + (size_t)row0 * lda;
    const __half* Bb = B + (size_t)col0 * ldb;
    const uint32_t sbase = smem_u32(sm);

    const int ldr = tid >> 3;           // row base (x4 iters of 32)
    const int ldcN = (tid & 7) * 8;     // halves offset within row (16B chunks)

    auto load_stage = [&](int k0, int st) {
        const uint32_t abase = sbase + st * (STAGE_H * 2);
        const uint32_t bbase = abase + A_SZH * 2;
#pragma unroll
        for (int i = 0; i < 4; i++) {
            const int r = ldr + i * 32;
            cp16(abase + (r * RS + ldcN) * 2, Ab + (size_t)r * lda + k0 + ldcN);
        }
#pragma unroll
        for (int i = 0; i < 4; i++) {
            const int r = ldr + i * 32;
            cp16(bbase + (r * RS + ldcN) * 2, Bb + (size_t)r * ldb + k0 + ldcN);
        }
        asm volatile("cp.async.commit_group;" ::: "memory");
    };

    float acc[2][8][4];
#pragma unroll
    for (int a = 0; a < 2; a++)
#pragma unroll
        for (int b = 0; b < 8; b++)
#pragma unroll
            for (int c = 0; c < 4; c++) acc[a][b][c] = 0.f;

    const int nk = K / BK;
    load_stage(0, 0);
    if (nk > 1) load_stage(BK, 1);

    const int g  = lane >> 2;           // 0..7
    const int tg = lane & 3;            // 0..3

    int st = 0;
    for (int t = 0; t < nk; t++) {
        if (t + 1 < nk) asm volatile("cp.async.wait_group 1;" ::: "memory");
        else            asm volatile("cp.async.wait_group 0;" ::: "memory");
        __syncthreads();

        if (t + 2 < nk) {
            int st2 = st + 2; if (st2 >= NSTAGE) st2 -= NSTAGE;
            load_stage((t + 2) * BK, st2);
        }

        const __half* sA_ = sm + st * STAGE_H;
        const __half* sB_ = sA_ + A_SZH;

#pragma unroll
        for (int ks = 0; ks < 4; ks++) {            // 4 x k16 = BK
            const int k = ks * 16;
            uint32_t a[2][4];
#pragma unroll
            for (int mt = 0; mt < 2; mt++) {
                const int rm = warp_m * 32 + mt * 16 + g;
                const __half* p = sA_ + rm * RS + k + tg * 2;
                a[mt][0] = *(const uint32_t*)(p);
                a[mt][1] = *(const uint32_t*)(p + 8 * RS);
                a[mt][2] = *(const uint32_t*)(p + 8);
                a[mt][3] = *(const uint32_t*)(p + 8 * RS + 8);
            }
#pragma unroll
            for (int nt = 0; nt < 8; nt++) {
                const int n = warp_n * 64 + nt * 8 + g;
                const __half* p = sB_ + n * RS + k + tg * 2;
                const uint32_t b0 = *(const uint32_t*)(p);
                const uint32_t b1 = *(const uint32_t*)(p + 8);
                mma_f16(acc[0][nt], a[0][0], a[0][1], a[0][2], a[0][3], b0, b1);
                mma_f16(acc[1][nt], a[1][0], a[1][1], a[1][2], a[1][3], b0, b1);
            }
        }
        st++; if (st >= NSTAGE) st -= NSTAGE;
    }

    // Epilogue
    if (out_half) {
        __half* C = (__half*)Cvoid + (size_t)batch * sC;
#pragma unroll
        for (int mt = 0; mt < 2; mt++)
#pragma unroll
            for (int half_ = 0; half_ < 2; half_++) {
                const int r = row0 + warp_m * 32 + mt * 16 + half_ * 8 + g;
                __half* Crow = C + (size_t)r * ldc;
#pragma unroll
                for (int nt = 0; nt < 8; nt++) {
                    const int cix = col0 + warp_n * 64 + nt * 8 + tg * 2;
                    float v0 = acc[mt][nt][half_ * 2 + 0] * alpha;
                    float v1 = acc[mt][nt][half_ * 2 + 1] * alpha;
                    if (bias) { v0 += bias[cix]; v1 += bias[cix + 1]; }
                    *(__half2*)&Crow[cix] = __floats2half2_rn(v0, v1);
                }
            }
    } else {
        float* C = (float*)Cvoid + (size_t)batch * sC;
        const float* R = resid ? resid + (size_t)batch * sC : nullptr;
#pragma unroll
        for (int mt = 0; mt < 2; mt++)
#pragma unroll
            for (int half_ = 0; half_ < 2; half_++) {
                const int r = row0 + warp_m * 32 + mt * 16 + half_ * 8 + g;
                float* Crow = C + (size_t)r * ldc;
                const float* Rrow = R ? R + (size_t)r * ldc : nullptr;
#pragma unroll
                for (int nt = 0; nt < 8; nt++) {
                    const int cix = col0 + warp_n * 64 + nt * 8 + tg * 2;
                    float v0 = acc[mt][nt][half_ * 2 + 0] * alpha;
                    float v1 = acc[mt][nt][half_ * 2 + 1] * alpha;
                    if (bias) { v0 += bias[cix]; v1 += bias[cix + 1]; }
                    if (Rrow) { v0 += Rrow[cix]; v1 += Rrow[cix + 1]; }
                    *(float2*)&Crow[cix] = make_float2(v0, v1);
                }
            }
    }
}

// ---------------------------------------------------------------------------
// Row softmax: fp32 logits -> fp16 probs
// ---------------------------------------------------------------------------
__global__ void softmax_kernel()
{
    const size_t row = blockIdx.x;
    const float4* p = (const float4*)(g_lg + row * (size_t)SS);
    __half2* q = (__half2*)(g_p + row * (size_t)SS);
    const int tid = threadIdx.x;

    float4 v = p[tid];
    float m = fmaxf(fmaxf(v.x, v.y), fmaxf(v.z, v.w));
    __shared__ float red[256];
    red[tid] = m;
    __syncthreads();
    for (int off = 128; off > 0; off >>= 1) {
        if (tid < off) red[tid] = fmaxf(red[tid], red[tid + off]);
        __syncthreads();
    }
    m = red[0];
    __syncthreads();
    v.x = expf(v.x - m); v.y = expf(v.y - m);
    v.z = expf(v.z - m); v.w = expf(v.w - m);
    float s = v.x + v.y + v.z + v.w;
    red[tid] = s;
    __syncthreads();
    for (int off = 128; off > 0; off >>= 1) {
        if (tid < off) red[tid] += red[tid + off];
        __syncthreads();
    }
    const float inv = 1.f / red[0];
    q[tid * 2 + 0] = __floats2half2_rn(v.x * inv, v.y * inv);
    q[tid * 2 + 1] = __floats2half2_rn(v.z * inv, v.w * inv);
}

// ---------------------------------------------------------------------------
// Launch
// ---------------------------------------------------------------------------
extern "C" void kernel_launch(void* const* d_in, const int* in_sizes, int n_in,
                              void* d_out, int out_size)
{
    const float* x   = (const float*)d_in[0];
    const float* gsc = (const float*)d_in[1];
    const float* gbi = (const float*)d_in[2];
    const float* Wq  = (const float*)d_in[3];
    const float* bq  = (const float*)d_in[4];
    const float* Wk  = (const float*)d_in[5];
    const float* bk  = (const float*)d_in[6];
    const float* Wv  = (const float*)d_in[7];
    const float* bv  = (const float*)d_in[8];
    const float* Wo  = (const float*)d_in[9];
    const float* bo  = (const float*)d_in[10];
    float* out = (float*)d_out;

    cudaFuncSetAttribute(mma_gemm, cudaFuncAttributeMaxDynamicSharedMemorySize,
                         SMEM_BYTES);

    __half *ft, *qkv, *vt, *pb, *at, *wt;
    float *lg, *bqkv;
    cudaGetSymbolAddress((void**)&ft,   g_ft);
    cudaGetSymbolAddress((void**)&qkv,  g_qkv);
    cudaGetSymbolAddress((void**)&vt,   g_vt);
    cudaGetSymbolAddress((void**)&lg,   g_lg);
    cudaGetSymbolAddress((void**)&pb,   g_p);
    cudaGetSymbolAddress((void**)&at,   g_at);
    cudaGetSymbolAddress((void**)&wt,   g_wt);
    cudaGetSymbolAddress((void**)&bqkv, g_bqkv);

    const long long sQKV = (long long)SS * 3 * CC;   // half elements
    const long long sBSS = (long long)SS * SS;       // elements (f32 or half)
    const long long sVT  = (long long)CC * SS;
    const long long sBSC = (long long)SS * CC;

    // 1) GroupNorm, weight transpose, bias pack
    gn_kernel<<<BB * GG, 256>>>(x, gsc, gbi);
    transpose_w<<<dim3(8, 8, 4), dim3(32, 8)>>>(Wq, Wk, Wv, Wo);
    pack_bias<<<1, 256>>>(bq, bk, bv);

    // 2) fused QKV projection: [32768,256] x [768,256]^T -> half [32768,768]
    mma_gemm<<<dim3((3 * CC) / BN, MS / BM, 1), 256, SMEM_BYTES>>>(
        ft, wt, bqkv, nullptr, qkv,
        CC, CC, CC, 3 * CC, 1.f, 1, 1, 0, 0, 0);

    // 3) logits = (1/16) Q K^T per batch -> f32
    mma_gemm<<<dim3(SS / BM, SS / BN, BB), 256, SMEM_BYTES>>>(
        qkv + 0, qkv + CC, nullptr, nullptr, lg,
        CC, 3 * CC, 3 * CC, SS, 0.0625f, 0, 0, sQKV, sQKV, sBSS);

    // 4) V transpose + softmax (f32 logits -> half probs)
    transpose_v<<<dim3(SS / 32, CC / 32, BB), dim3(32, 8)>>>();
    softmax_kernel<<<BB * SS, 256>>>();

    // 5) attn = P V per batch: [1024,1024]h x [256,1024]h^T -> half
    mma_gemm<<<dim3(SS / BM, CC / BN, BB), 256, SMEM_BYTES>>>(
        pb, vt, nullptr, nullptr, at,
        SS, SS, SS, CC, 1.f, 1, 0, sBSS, sVT, sBSC);

    // 6) out = attn Wo + bo + x -> f32
    mma_gemm<<<dim3(CC / BN, MS / BM, 1), 256, SMEM_BYTES>>>(
        at, wt + 3 * CC * CC, bo, x, out,
        CC, CC, CC, CC, 1.f, 0, 1, 0, 0, 0);
}